// round 15
// baseline (speedup 1.0000x reference)
#include <cuda_runtime.h>
#include <cuda_bf16.h>
#include <math.h>

typedef unsigned int u32;

// ---------------------------------------------------------------------------
// Problem: B=8, S=1024, D=512, H=8, dh=64, MAX_POS=128
// ---------------------------------------------------------------------------

// split-bf16 Q/K/V, layout [bh][s][d]; Q pre-scaled by 1/8
static __device__ __nv_bfloat16 g_Qh[8*8*1024*64];
static __device__ __nv_bfloat16 g_Ql[8*8*1024*64];
static __device__ __nv_bfloat16 g_Kh[8*8*1024*64];
static __device__ __nv_bfloat16 g_Kl[8*8*1024*64];
static __device__ __nv_bfloat16 g_Vh[8*8*1024*64];
static __device__ __nv_bfloat16 g_Vl[8*8*1024*64];
// V transposed: [bh][d][s]
static __device__ __nv_bfloat16 g_Vth[8*8*64*1024];
static __device__ __nv_bfloat16 g_Vtl[8*8*64*1024];
static __device__ float g_O[8192*512];            // [b,s,h*64+d]
static __device__ int g_maxKi[64];                // per-bh max ||K_k|| (int bits)

// ---------------------------- helpers --------------------------------------
__device__ __forceinline__ u32 pack2(__nv_bfloat16 x, __nv_bfloat16 y){
    __nv_bfloat162 t; t.x = x; t.y = y;
    return *reinterpret_cast<u32*>(&t);
}
__device__ __forceinline__ float2 unpack2(u32 w){
    __nv_bfloat162 t = *reinterpret_cast<__nv_bfloat162*>(&w);
    return make_float2(__bfloat162float(t.x), __bfloat162float(t.y));
}
__device__ __forceinline__ void split_bf(float v, __nv_bfloat16& h, __nv_bfloat16& l){
    h = __float2bfloat16(v);
    l = __float2bfloat16(v - __bfloat162float(h));
}
__device__ __forceinline__ void mma16816(float c[4], u32 a0,u32 a1,u32 a2,u32 a3,
                                         u32 b0,u32 b1){
    asm volatile(
      "mma.sync.aligned.m16n8k16.row.col.f32.bf16.bf16.f32 "
      "{%0,%1,%2,%3}, {%4,%5,%6,%7}, {%8,%9}, {%0,%1,%2,%3};"
      : "+f"(c[0]), "+f"(c[1]), "+f"(c[2]), "+f"(c[3])
      : "r"(a0), "r"(a1), "r"(a2), "r"(a3), "r"(b0), "r"(b1));
}

// ======================= Tensor-core GEMM (register-prefetch pipelined) ====
// C[m,n] = A[m,:512] @ W[:512,n] + bias[n]
// MODE 0: A = x,  N=1536, epilogue split-scatters into g_Q/K/V (Q x 1/8).
// MODE 1: A = g_O, N=512, epilogue writes fp32 + bias to C.
// Tile 128x128x32; 256 thr = 8 warps (4m x 2n); warp tile 32x64.
// Tile k+1's A/W global data is prefetched into registers during tile k's
// convert+compute, hiding the LDG round trip (no cp.async, no alloc risk).
#define OFF_AH 0
#define OFF_AL 10240
#define OFF_BH 20480
#define OFF_BL 30720
#define OFF_WF 40960
#define GEMM_SMEM (40960 + 32*132*4)   // 57856 B

template<int MODE>
__global__ __launch_bounds__(256)
void gemm_tc3(const float* __restrict__ Ain,
              const float* __restrict__ W,
              const float* __restrict__ bias,
              float* __restrict__ C)
{
    extern __shared__ char gsm[];
    __nv_bfloat16* Ah = (__nv_bfloat16*)(gsm + OFF_AH);
    __nv_bfloat16* Al = (__nv_bfloat16*)(gsm + OFF_AL);
    __nv_bfloat16* Bh = (__nv_bfloat16*)(gsm + OFF_BH);
    __nv_bfloat16* Bl = (__nv_bfloat16*)(gsm + OFF_BL);
    float*         Wf = (float*)        (gsm + OFF_WF);

    constexpr int NSTR = (MODE == 0) ? 1536 : 512;
    const float* A = (MODE == 0) ? Ain : g_O;

    const int t = threadIdx.x;
    const int lane = t & 31, w = t >> 5;
    const int grp = lane >> 2, cc = lane & 3;
    const int wm = w & 3, wn = w >> 2;
    const int n0 = blockIdx.x * 128;
    const int m0 = blockIdx.y * 128;

    if (MODE == 0 && blockIdx.x == 0 && blockIdx.y == 0 && t < 64) g_maxKi[t] = 0;

    float c[2][8][4];
#pragma unroll
    for (int mi = 0; mi < 2; mi++)
#pragma unroll
        for (int ni = 0; ni < 8; ni++)
#pragma unroll
            for (int e = 0; e < 4; e++) c[mi][ni][e] = 0.f;

    // prefetch registers for tile data
    float4 pA[4], pW[4];
#pragma unroll
    for (int it = 0; it < 4; it++) {
        int i = t + it * 256;
        int m = i >> 3, kv = (i & 7) * 4;
        pA[it] = *(const float4*)(A + (size_t)(m0 + m) * 512 + kv);
        int k = i >> 5, nv = (i & 31) * 4;
        pW[it] = *(const float4*)(W + (size_t)k * NSTR + n0 + nv);
    }

    for (int k0 = 0; k0 < 512; k0 += 32) {
        __syncthreads();   // previous compute done reading smem
        // ---- store prefetched A (split) + W (f32) ----
#pragma unroll
        for (int it = 0; it < 4; it++) {
            int i = t + it * 256;
            int m = i >> 3, kv = (i & 7) * 4;
            float4 v = pA[it];
            __nv_bfloat16 h0,l0,h1,l1,h2,l2,h3,l3;
            split_bf(v.x, h0, l0); split_bf(v.y, h1, l1);
            split_bf(v.z, h2, l2); split_bf(v.w, h3, l3);
            *(u32*)&Ah[m * 40 + kv]     = pack2(h0, h1);
            *(u32*)&Ah[m * 40 + kv + 2] = pack2(h2, h3);
            *(u32*)&Al[m * 40 + kv]     = pack2(l0, l1);
            *(u32*)&Al[m * 40 + kv + 2] = pack2(l2, l3);
            int k = i >> 5, nv = (i & 31) * 4;
            *(float4*)&Wf[k * 132 + nv] = pW[it];
        }
        __syncthreads();
        // ---- convert-transpose W -> Bh/Bl [n][40] ----
#pragma unroll
        for (int it = 0; it < 4; it++) {
            int i = t + it * 256;
            int n = i & 127, kb = (i >> 7) * 4;
            float v0 = Wf[(kb + 0) * 132 + n];
            float v1 = Wf[(kb + 1) * 132 + n];
            float v2 = Wf[(kb + 2) * 132 + n];
            float v3 = Wf[(kb + 3) * 132 + n];
            __nv_bfloat16 h0,l0,h1,l1,h2,l2,h3,l3;
            split_bf(v0, h0, l0); split_bf(v1, h1, l1);
            split_bf(v2, h2, l2); split_bf(v3, h3, l3);
            *(u32*)&Bh[n * 40 + kb]     = pack2(h0, h1);
            *(u32*)&Bh[n * 40 + kb + 2] = pack2(h2, h3);
            *(u32*)&Bl[n * 40 + kb]     = pack2(l0, l1);
            *(u32*)&Bl[n * 40 + kb + 2] = pack2(l2, l3);
        }
        // ---- prefetch next tile (overlaps convert-sync + compute) ----
        if (k0 + 32 < 512) {
            int k0n = k0 + 32;
#pragma unroll
            for (int it = 0; it < 4; it++) {
                int i = t + it * 256;
                int m = i >> 3, kv = (i & 7) * 4;
                pA[it] = *(const float4*)(A + (size_t)(m0 + m) * 512 + k0n + kv);
                int k = i >> 5, nv = (i & 31) * 4;
                pW[it] = *(const float4*)(W + (size_t)(k0n + k) * NSTR + n0 + nv);
            }
        }
        __syncthreads();

        // ---- compute (fragment loads conflict-free at stride 40) ----
#pragma unroll
        for (int ks = 0; ks < 2; ks++) {
            int col = ks * 16 + 2 * cc;
            u32 ah[2][4], al[2][4];
#pragma unroll
            for (int mi = 0; mi < 2; mi++) {
                int r = wm * 32 + mi * 16 + grp;
                ah[mi][0] = *(u32*)&Ah[r * 40 + col];
                ah[mi][1] = *(u32*)&Ah[(r + 8) * 40 + col];
                ah[mi][2] = *(u32*)&Ah[r * 40 + col + 8];
                ah[mi][3] = *(u32*)&Ah[(r + 8) * 40 + col + 8];
                al[mi][0] = *(u32*)&Al[r * 40 + col];
                al[mi][1] = *(u32*)&Al[(r + 8) * 40 + col];
                al[mi][2] = *(u32*)&Al[r * 40 + col + 8];
                al[mi][3] = *(u32*)&Al[(r + 8) * 40 + col + 8];
            }
#pragma unroll
            for (int ni = 0; ni < 8; ni++) {
                int nr = wn * 64 + ni * 8 + grp;
                u32 bh0 = *(u32*)&Bh[nr * 40 + col];
                u32 bh1 = *(u32*)&Bh[nr * 40 + col + 8];
                u32 bl0 = *(u32*)&Bl[nr * 40 + col];
                u32 bl1 = *(u32*)&Bl[nr * 40 + col + 8];
#pragma unroll
                for (int mi = 0; mi < 2; mi++) {
                    mma16816(c[mi][ni], ah[mi][0],ah[mi][1],ah[mi][2],ah[mi][3], bh0,bh1);
                    mma16816(c[mi][ni], ah[mi][0],ah[mi][1],ah[mi][2],ah[mi][3], bl0,bl1);
                    mma16816(c[mi][ni], al[mi][0],al[mi][1],al[mi][2],al[mi][3], bh0,bh1);
                }
            }
        }
    }

    // ---- epilogue ----
#pragma unroll
    for (int mi = 0; mi < 2; mi++) {
        int r0 = m0 + wm * 32 + mi * 16 + grp;
#pragma unroll
        for (int ni = 0; ni < 8; ni++) {
            int ng = n0 + wn * 64 + ni * 8 + 2 * cc;
            float b0 = bias[ng], b1 = bias[ng + 1];
            if (MODE == 0) {
                int part = ng >> 9;
                int rr = ng & 511;
                int hd = rr >> 6, d = rr & 63;
                float sc = (part == 0) ? 0.125f : 1.f;
                __nv_bfloat16* H = (part == 0) ? g_Qh : (part == 1) ? g_Kh : g_Vh;
                __nv_bfloat16* L = (part == 0) ? g_Ql : (part == 1) ? g_Kl : g_Vl;
#pragma unroll
                for (int rr2 = 0; rr2 < 2; rr2++) {
                    int m = r0 + rr2 * 8;
                    int bb = m >> 10, s = m & 1023;
                    float v0 = (c[mi][ni][2*rr2 + 0] + b0) * sc;
                    float v1 = (c[mi][ni][2*rr2 + 1] + b1) * sc;
                    __nv_bfloat16 h0,l0,h1,l1;
                    split_bf(v0, h0, l0); split_bf(v1, h1, l1);
                    size_t off = ((size_t)(bb*8 + hd) * 1024 + s) * 64 + d;
                    *(u32*)(H + off) = pack2(h0, h1);
                    *(u32*)(L + off) = pack2(l0, l1);
                }
            } else {
#pragma unroll
                for (int rr2 = 0; rr2 < 2; rr2++) {
                    int m = r0 + rr2 * 8;
                    float2 v = make_float2(c[mi][ni][2*rr2 + 0] + b0,
                                           c[mi][ni][2*rr2 + 1] + b1);
                    *(float2*)(C + (size_t)m * 512 + ng) = v;
                }
            }
        }
    }
}

// ======================= Kernel 1b: V transpose + K norms ==================
__global__ __launch_bounds__(256)
void vtrans_kernel()
{
    __shared__ __nv_bfloat16 th[64][72];
    __shared__ __nv_bfloat16 tl[64][72];
    const int t = threadIdx.x;
    const int s0 = blockIdx.x * 64;
    const int bh = blockIdx.y;

    for (int i = t; i < 2048; i += 256) {
        int sl = i >> 5, dp = i & 31;
        size_t src = ((size_t)bh * 1024 + s0 + sl) * 64 + 2*dp;
        *(u32*)&th[sl][2*dp] = *(const u32*)(g_Vh + src);
        *(u32*)&tl[sl][2*dp] = *(const u32*)(g_Vl + src);
    }
    __syncthreads();
    for (int i = t; i < 2048; i += 256) {
        int d = i >> 5, sp = i & 31;
        size_t dst = ((size_t)bh * 64 + d) * 1024 + s0 + 2*sp;
        *(u32*)(g_Vth + dst) = pack2(th[2*sp][d], th[2*sp+1][d]);
        *(u32*)(g_Vtl + dst) = pack2(tl[2*sp][d], tl[2*sp+1][d]);
    }
    if (t < 64) {
        float s = 0.f;
        size_t base = ((size_t)bh * 1024 + s0 + t) * 64;
        for (int dp = 0; dp < 32; dp++) {
            float2 h = unpack2(*(const u32*)(g_Kh + base + 2*dp));
            float2 l = unpack2(*(const u32*)(g_Kl + base + 2*dp));
            float v0 = h.x + l.x, v1 = h.y + l.y;
            s += v0*v0 + v1*v1;
        }
        atomicMax(&g_maxKi[bh], __float_as_int(sqrtf(s)));
    }
}

// ======================= Kernel 2: attention + K/V register prefetch =======
// (byte-identical to the R14 passing version)
#define OFF_QH 0
#define OFF_QL 9216
#define OFF_KH 18432
#define OFF_KL 27648
#define OFF_VH 36864
#define OFF_VL 46080
#define OFF_QP 55296
#define OFF_AP 122880
#define OFF_MSK 190464
#define OFF_RED 190720
#define ATTN_SMEM (190720 + 4096)

__global__ __launch_bounds__(512)
void attn_kernel(const int* __restrict__ mask,
                 const float* __restrict__ posK,
                 const float* __restrict__ posV)
{
    extern __shared__ char sm[];
    __nv_bfloat16* QH = (__nv_bfloat16*)(sm + OFF_QH);
    __nv_bfloat16* QL = (__nv_bfloat16*)(sm + OFF_QL);
    __nv_bfloat16* KH = (__nv_bfloat16*)(sm + OFF_KH);
    __nv_bfloat16* KL = (__nv_bfloat16*)(sm + OFF_KL);
    __nv_bfloat16* VH = (__nv_bfloat16*)(sm + OFF_VH);
    __nv_bfloat16* VL = (__nv_bfloat16*)(sm + OFF_VL);
    float* QP  = (float*)(sm + OFF_QP);
    float* AP  = (float*)(sm + OFF_AP);
    float* MSK = (float*)(sm + OFF_MSK);
    float* RED = (float*)(sm + OFF_RED);

    const int t = threadIdx.x;
    const int w = t >> 5, lane = t & 31, grp = lane >> 2, cc = lane & 3;
    const int wq = w & 3, wn = w >> 2;
    const int q0 = blockIdx.x * 64;
    const int bh = blockIdx.y;
    const int bb = bh >> 3, hh = bh & 7;
    const int r_lo = wq * 16 + grp;
    const int qg0 = q0 + r_lo, qg1 = qg0 + 8;
    const int sk0 = t >> 5, sdp = (t & 31);

    for (int i = t; i < 2048; i += 512) {
        int r = i >> 5, dp = i & 31;
        size_t src = ((size_t)bh * 1024 + q0 + r) * 64 + 2*dp;
        *(u32*)&QH[r*72 + 2*dp] = *(const u32*)(g_Qh + src);
        *(u32*)&QL[r*72 + 2*dp] = *(const u32*)(g_Ql + src);
    }
    for (int i = t; i < 64*264; i += 512) AP[i] = 0.f;
    __syncthreads();

    u32 qa_h[4][4], qa_l[4][4];
#pragma unroll
    for (int kc = 0; kc < 4; kc++) {
        int col = 16*kc + 2*cc;
        qa_h[kc][0] = *(u32*)&QH[ r_lo    *72 + col];
        qa_h[kc][1] = *(u32*)&QH[(r_lo+8)*72 + col];
        qa_h[kc][2] = *(u32*)&QH[ r_lo    *72 + col + 8];
        qa_h[kc][3] = *(u32*)&QH[(r_lo+8)*72 + col + 8];
        qa_l[kc][0] = *(u32*)&QL[ r_lo    *72 + col];
        qa_l[kc][1] = *(u32*)&QL[(r_lo+8)*72 + col];
        qa_l[kc][2] = *(u32*)&QL[ r_lo    *72 + col + 8];
        qa_l[kc][3] = *(u32*)&QL[(r_lo+8)*72 + col + 8];
    }

    for (int rt = 0; rt < 5; rt++) {
        int r0 = rt * 64;
        __syncthreads();
        for (int i = t; i < 2048; i += 512) {
            int r = i >> 5, dp = i & 31;
            int rg = r0 + r;
            float2 pv = (rg < 257) ? *(const float2*)(posK + rg*64 + 2*dp)
                                   : make_float2(0.f, 0.f);
            __nv_bfloat16 h0,l0,h1,l1;
            split_bf(pv.x, h0, l0); split_bf(pv.y, h1, l1);
            *(u32*)&KH[r*72 + 2*dp] = pack2(h0, h1);
            *(u32*)&KL[r*72 + 2*dp] = pack2(l0, l1);
        }
        __syncthreads();
        float c[2][4];
#pragma unroll
        for (int n4 = 0; n4 < 2; n4++)
#pragma unroll
            for (int e = 0; e < 4; e++) c[n4][e] = 0.f;
#pragma unroll
        for (int n4 = 0; n4 < 2; n4++) {
            int nc = 2*wn + n4;
#pragma unroll
            for (int kc = 0; kc < 4; kc++) {
                const __nv_bfloat16* ph = KH + (8*nc+grp)*72 + 16*kc + 2*cc;
                const __nv_bfloat16* pl = KL + (8*nc+grp)*72 + 16*kc + 2*cc;
                u32 bh0 = *(const u32*)ph, bh1 = *(const u32*)(ph + 8);
                u32 bl0 = *(const u32*)pl, bl1 = *(const u32*)(pl + 8);
                mma16816(c[n4], qa_h[kc][0],qa_h[kc][1],qa_h[kc][2],qa_h[kc][3], bh0,bh1);
                mma16816(c[n4], qa_h[kc][0],qa_h[kc][1],qa_h[kc][2],qa_h[kc][3], bl0,bl1);
                mma16816(c[n4], qa_l[kc][0],qa_l[kc][1],qa_l[kc][2],qa_l[kc][3], bh0,bh1);
            }
        }
#pragma unroll
        for (int n4 = 0; n4 < 2; n4++) {
            int nc = 2*wn + n4;
            int r = r0 + 8*nc + 2*cc;
            if (r < 257) {
                QP[ r_lo    *264 + r] = c[n4][0];
                QP[(r_lo+8) *264 + r] = c[n4][2];
            }
            if (r + 1 < 257) {
                QP[ r_lo    *264 + r + 1] = c[n4][1];
                QP[(r_lo+8) *264 + r + 1] = c[n4][3];
            }
        }
    }

    __syncthreads();
    {
        const float maxK = __int_as_float(g_maxKi[bh]);
        if (t < 64) {
            float sn = 0.f;
            for (int dp = 0; dp < 32; dp++) {
                float2 h = unpack2(*(u32*)&QH[t*72 + 2*dp]);
                float2 l = unpack2(*(u32*)&QL[t*72 + 2*dp]);
                float v0 = h.x + l.x, v1 = h.y + l.y;
                sn += v0*v0 + v1*v1;
            }
            float mq = -1e30f;
            for (int r = 0; r < 257; r++) mq = fmaxf(mq, QP[t*264 + r]);
            RED[t] = sqrtf(sn) * maxK + mq + 0.5f;
        }
    }
    __syncthreads();
    const float z0 = RED[r_lo], z1 = RED[r_lo + 8];
    __syncthreads();

    float o[8][4];
#pragma unroll
    for (int nd = 0; nd < 8; nd++)
#pragma unroll
        for (int e = 0; e < 4; e++) o[nd][e] = 0.f;
    float bin0a = 0.f, bin0b = 0.f, bin256a = 0.f, bin256b = 0.f;
    float ls0 = 0.f, ls1 = 0.f;

    u32 pK[4][2], pV[4][2];
#pragma unroll
    for (int j = 0; j < 4; j++) {
        int k = sk0 + 16*j;
        size_t srcK = ((size_t)bh * 1024 + k) * 64 + 2*sdp;
        size_t srcV = ((size_t)bh * 64 + k) * 1024 + 2*sdp;
        pK[j][0] = *(const u32*)(g_Kh + srcK);
        pK[j][1] = *(const u32*)(g_Kl + srcK);
        pV[j][0] = *(const u32*)(g_Vth + srcV);
        pV[j][1] = *(const u32*)(g_Vtl + srcV);
    }
    int pmsk = (t < 64) ? mask[bb*1024 + t] : 0;

    for (int kt = 0; kt < 16; kt++) {
        __syncthreads();
#pragma unroll
        for (int j = 0; j < 4; j++) {
            int k = sk0 + 16*j;
            *(u32*)&KH[k*72 + 2*sdp] = pK[j][0];
            *(u32*)&KL[k*72 + 2*sdp] = pK[j][1];
            *(u32*)&VH[k*72 + 2*sdp] = pV[j][0];
            *(u32*)&VL[k*72 + 2*sdp] = pV[j][1];
        }
        if (t < 64) MSK[t] = pmsk ? 0.f : -1e30f;
        __syncthreads();
        if (kt < 15) {
            int k0n = (kt + 1) * 64;
#pragma unroll
            for (int j = 0; j < 4; j++) {
                int k = sk0 + 16*j;
                size_t srcK = ((size_t)bh * 1024 + k0n + k) * 64 + 2*sdp;
                size_t srcV = ((size_t)bh * 64 + k) * 1024 + k0n + 2*sdp;
                pK[j][0] = *(const u32*)(g_Kh + srcK);
                pK[j][1] = *(const u32*)(g_Kl + srcK);
                pV[j][0] = *(const u32*)(g_Vth + srcV);
                pV[j][1] = *(const u32*)(g_Vtl + srcV);
            }
            if (t < 64) pmsk = mask[bb*1024 + k0n + t];
        }

        const int k0 = kt * 64;
        float c[2][4];
#pragma unroll
        for (int n4 = 0; n4 < 2; n4++)
#pragma unroll
            for (int e = 0; e < 4; e++) c[n4][e] = 0.f;
#pragma unroll
        for (int n4 = 0; n4 < 2; n4++) {
            int nc = 2*wn + n4;
#pragma unroll
            for (int kc = 0; kc < 4; kc++) {
                const __nv_bfloat16* ph = KH + (8*nc+grp)*72 + 16*kc + 2*cc;
                const __nv_bfloat16* pl = KL + (8*nc+grp)*72 + 16*kc + 2*cc;
                u32 bh0 = *(const u32*)ph, bh1 = *(const u32*)(ph + 8);
                u32 bl0 = *(const u32*)pl, bl1 = *(const u32*)(pl + 8);
                mma16816(c[n4], qa_h[kc][0],qa_h[kc][1],qa_h[kc][2],qa_h[kc][3], bh0,bh1);
                mma16816(c[n4], qa_h[kc][0],qa_h[kc][1],qa_h[kc][2],qa_h[kc][3], bl0,bl1);
                mma16816(c[n4], qa_l[kc][0],qa_l[kc][1],qa_l[kc][2],qa_l[kc][3], bh0,bh1);
            }
        }

        u32 ph[2][2], pl[2][2];
#pragma unroll
        for (int n4 = 0; n4 < 2; n4++) {
            int nc = 2*wn + n4;
            int kg = k0 + 8*nc + 2*cc;
            float bias0 = MSK[8*nc + 2*cc], bias1 = MSK[8*nc + 2*cc + 1];
            int dA0 = kg     - qg0, dA1 = kg + 1 - qg0;
            int dB0 = kg     - qg1, dB1 = kg + 1 - qg1;
            float s00 = c[n4][0] + QP[ r_lo   *264 + min(max(dA0,-128),128)+128] + bias0;
            float s01 = c[n4][1] + QP[ r_lo   *264 + min(max(dA1,-128),128)+128] + bias1;
            float s10 = c[n4][2] + QP[(r_lo+8)*264 + min(max(dB0,-128),128)+128] + bias0;
            float s11 = c[n4][3] + QP[(r_lo+8)*264 + min(max(dB1,-128),128)+128] + bias1;
            float p00 = __expf(s00 - z0), p01 = __expf(s01 - z0);
            float p10 = __expf(s10 - z1), p11 = __expf(s11 - z1);
            ls0 += p00 + p01;
            ls1 += p10 + p11;
            if (dA0 <= -128) bin0a += p00; else if (dA0 >= 128) bin256a += p00;
            else AP[ r_lo   *264 + dA0 + 128] = p00;
            if (dA1 <= -128) bin0a += p01; else if (dA1 >= 128) bin256a += p01;
            else AP[ r_lo   *264 + dA1 + 128] = p01;
            if (dB0 <= -128) bin0b += p10; else if (dB0 >= 128) bin256b += p10;
            else AP[(r_lo+8)*264 + dB0 + 128] = p10;
            if (dB1 <= -128) bin0b += p11; else if (dB1 >= 128) bin256b += p11;
            else AP[(r_lo+8)*264 + dB1 + 128] = p11;
            __nv_bfloat16 h00,l00,h01,l01,h10,l10,h11,l11;
            split_bf(p00, h00, l00); split_bf(p01, h01, l01);
            split_bf(p10, h10, l10); split_bf(p11, h11, l11);
            ph[n4][0] = pack2(h00, h01); pl[n4][0] = pack2(l00, l01);
            ph[n4][1] = pack2(h10, h11); pl[n4][1] = pack2(l10, l11);
        }

#pragma unroll
        for (int nd = 0; nd < 8; nd++) {
            const __nv_bfloat16* pvh = VH + (8*nd+grp)*72 + 16*wn + 2*cc;
            const __nv_bfloat16* pvl = VL + (8*nd+grp)*72 + 16*wn + 2*cc;
            u32 bh0 = *(const u32*)pvh, bh1 = *(const u32*)(pvh + 8);
            u32 bl0 = *(const u32*)pvl, bl1 = *(const u32*)(pvl + 8);
            mma16816(o[nd], ph[0][0], ph[0][1], ph[1][0], ph[1][1], bh0, bh1);
            mma16816(o[nd], ph[0][0], ph[0][1], ph[1][0], ph[1][1], bl0, bl1);
            mma16816(o[nd], pl[0][0], pl[0][1], pl[1][0], pl[1][1], bh0, bh1);
        }
    }

    bin0a   += __shfl_xor_sync(0xffffffffu, bin0a, 1);
    bin0a   += __shfl_xor_sync(0xffffffffu, bin0a, 2);
    bin0b   += __shfl_xor_sync(0xffffffffu, bin0b, 1);
    bin0b   += __shfl_xor_sync(0xffffffffu, bin0b, 2);
    bin256a += __shfl_xor_sync(0xffffffffu, bin256a, 1);
    bin256a += __shfl_xor_sync(0xffffffffu, bin256a, 2);
    bin256b += __shfl_xor_sync(0xffffffffu, bin256b, 1);
    bin256b += __shfl_xor_sync(0xffffffffu, bin256b, 2);
    ls0 += __shfl_xor_sync(0xffffffffu, ls0, 1);
    ls0 += __shfl_xor_sync(0xffffffffu, ls0, 2);
    ls1 += __shfl_xor_sync(0xffffffffu, ls1, 1);
    ls1 += __shfl_xor_sync(0xffffffffu, ls1, 2);
    if (cc == 0) {
        atomicAdd(&AP[ r_lo   *264 + 0],   bin0a);
        atomicAdd(&AP[ r_lo   *264 + 256], bin256a);
        atomicAdd(&AP[(r_lo+8)*264 + 0],   bin0b);
        atomicAdd(&AP[(r_lo+8)*264 + 256], bin256b);
        RED[wn*64 + r_lo]     = ls0;
        RED[wn*64 + r_lo + 8] = ls1;
    }
    __syncthreads();
    const float inv0 = 1.f / (RED[r_lo]       + RED[64 + r_lo] +
                              RED[128 + r_lo] + RED[192 + r_lo]);
    const float inv1 = 1.f / (RED[r_lo + 8]       + RED[64 + r_lo + 8] +
                              RED[128 + r_lo + 8] + RED[192 + r_lo + 8]);

    for (int rt = 0; rt < 5; rt++) {
        int r0 = rt * 64;
        for (int i = t; i < 4096; i += 512) {
            int r = i >> 6, d = i & 63;
            int rg = r0 + r;
            float v = (rg < 257) ? posV[rg*64 + d] : 0.f;
            __nv_bfloat16 hb, lb;
            split_bf(v, hb, lb);
            VH[d*72 + r] = hb;
            VL[d*72 + r] = lb;
        }
        __syncthreads();
        {
            int rA = r0 + 16*wn + 2*cc;
            float v00 = (rA     < 257) ? AP[ r_lo   *264 + rA]     : 0.f;
            float v01 = (rA + 1 < 257) ? AP[ r_lo   *264 + rA + 1] : 0.f;
            float v10 = (rA     < 257) ? AP[(r_lo+8)*264 + rA]     : 0.f;
            float v11 = (rA + 1 < 257) ? AP[(r_lo+8)*264 + rA + 1] : 0.f;
            float v20 = (rA + 8 < 257) ? AP[ r_lo   *264 + rA + 8] : 0.f;
            float v21 = (rA + 9 < 257) ? AP[ r_lo   *264 + rA + 9] : 0.f;
            float v30 = (rA + 8 < 257) ? AP[(r_lo+8)*264 + rA + 8] : 0.f;
            float v31 = (rA + 9 < 257) ? AP[(r_lo+8)*264 + rA + 9] : 0.f;
            __nv_bfloat16 h[8], l[8];
            split_bf(v00, h[0], l[0]); split_bf(v01, h[1], l[1]);
            split_bf(v10, h[2], l[2]); split_bf(v11, h[3], l[3]);
            split_bf(v20, h[4], l[4]); split_bf(v21, h[5], l[5]);
            split_bf(v30, h[6], l[6]); split_bf(v31, h[7], l[7]);
            u32 ah0 = pack2(h[0], h[1]), ah1 = pack2(h[2], h[3]);
            u32 ah2 = pack2(h[4], h[5]), ah3 = pack2(h[6], h[7]);
            u32 al0 = pack2(l[0], l[1]), al1 = pack2(l[2], l[3]);
            u32 al2 = pack2(l[4], l[5]), al3 = pack2(l[6], l[7]);
#pragma unroll
            for (int nd = 0; nd < 8; nd++) {
                const __nv_bfloat16* pvh = VH + (8*nd+grp)*72 + 16*wn + 2*cc;
                const __nv_bfloat16* pvl = VL + (8*nd+grp)*72 + 16*wn + 2*cc;
                u32 bh0 = *(const u32*)pvh, bh1 = *(const u32*)(pvh + 8);
                u32 bl0 = *(const u32*)pvl, bl1 = *(const u32*)(pvl + 8);
                mma16816(o[nd], ah0, ah1, ah2, ah3, bh0, bh1);
                mma16816(o[nd], ah0, ah1, ah2, ah3, bl0, bl1);
                mma16816(o[nd], al0, al1, al2, al3, bh0, bh1);
            }
        }
        __syncthreads();
    }

    float* SC = QP;
    if (wn > 0) {
#pragma unroll
        for (int nd = 0; nd < 8; nd++)
            *(float4*)&SC[(wn-1)*4096 + wq*1024 + nd*128 + lane*4] = *(float4*)&o[nd][0];
    }
    __syncthreads();
    if (wn == 0) {
#pragma unroll
        for (int nd = 0; nd < 8; nd++) {
            float4 p1 = *(float4*)&SC[        wq*1024 + nd*128 + lane*4];
            float4 p2 = *(float4*)&SC[4096  + wq*1024 + nd*128 + lane*4];
            float4 p3 = *(float4*)&SC[8192  + wq*1024 + nd*128 + lane*4];
            int d = hh*64 + 8*nd + 2*cc;
            float2 s0 = make_float2((o[nd][0] + p1.x + p2.x + p3.x) * inv0,
                                    (o[nd][1] + p1.y + p2.y + p3.y) * inv0);
            float2 s1 = make_float2((o[nd][2] + p1.z + p2.z + p3.z) * inv1,
                                    (o[nd][3] + p1.w + p2.w + p3.w) * inv1);
            *(float2*)&g_O[((size_t)bb*1024 + q0 + r_lo    ) * 512 + d] = s0;
            *(float2*)&g_O[((size_t)bb*1024 + q0 + r_lo + 8) * 512 + d] = s1;
        }
    }
}

// ============================== launcher ===================================
extern "C" void kernel_launch(void* const* d_in, const int* in_sizes, int n_in,
                              void* d_out, int out_size)
{
    const float* x     = (const float*)d_in[0];
    const int*   mask  = (const int*)  d_in[1];
    const float* W_in  = (const float*)d_in[2];
    const float* b_in  = (const float*)d_in[3];
    const float* W_out = (const float*)d_in[4];
    const float* b_out = (const float*)d_in[5];
    const float* posK  = (const float*)d_in[6];
    const float* posV  = (const float*)d_in[7];
    float* out = (float*)d_out;
    (void)in_sizes; (void)n_in; (void)out_size;

    cudaFuncSetAttribute(attn_kernel,
                         cudaFuncAttributeMaxDynamicSharedMemorySize, ATTN_SMEM);
    cudaFuncSetAttribute(gemm_tc3<0>,
                         cudaFuncAttributeMaxDynamicSharedMemorySize, GEMM_SMEM);
    cudaFuncSetAttribute(gemm_tc3<1>,
                         cudaFuncAttributeMaxDynamicSharedMemorySize, GEMM_SMEM);

    gemm_tc3<0><<<dim3(12, 64), 256, GEMM_SMEM>>>(x, W_in, b_in, nullptr);
    vtrans_kernel<<<dim3(16, 64), 256>>>();
    attn_kernel<<<dim3(16, 64), 512, ATTN_SMEM>>>(mask, posK, posV);
    gemm_tc3<1><<<dim3(4, 64), 256, GEMM_SMEM>>>(nullptr, W_out, b_out, out);
}

// round 16
// speedup vs baseline: 1.1087x; 1.1087x over previous
#include <cuda_runtime.h>
#include <cuda_bf16.h>
#include <math.h>

typedef unsigned int u32;

// ---------------------------------------------------------------------------
// Problem: B=8, S=1024, D=512, H=8, dh=64, MAX_POS=128
// ---------------------------------------------------------------------------

// split-bf16 Q/K/V, layout [bh][s][d]; Q pre-scaled by 1/8
static __device__ __nv_bfloat16 g_Qh[8*8*1024*64];
static __device__ __nv_bfloat16 g_Ql[8*8*1024*64];
static __device__ __nv_bfloat16 g_Kh[8*8*1024*64];
static __device__ __nv_bfloat16 g_Kl[8*8*1024*64];
static __device__ __nv_bfloat16 g_Vh[8*8*1024*64];
static __device__ __nv_bfloat16 g_Vl[8*8*1024*64];
// V transposed: [bh][d][s]
static __device__ __nv_bfloat16 g_Vth[8*8*64*1024];
static __device__ __nv_bfloat16 g_Vtl[8*8*64*1024];
static __device__ float g_O[8192*512];            // [b,s,h*64+d]
static __device__ int g_maxKi[64];                // per-bh max ||K_k|| (int bits)

// ---------------------------- helpers --------------------------------------
__device__ __forceinline__ u32 pack2(__nv_bfloat16 x, __nv_bfloat16 y){
    __nv_bfloat162 t; t.x = x; t.y = y;
    return *reinterpret_cast<u32*>(&t);
}
__device__ __forceinline__ float2 unpack2(u32 w){
    __nv_bfloat162 t = *reinterpret_cast<__nv_bfloat162*>(&w);
    return make_float2(__bfloat162float(t.x), __bfloat162float(t.y));
}
__device__ __forceinline__ void split_bf(float v, __nv_bfloat16& h, __nv_bfloat16& l){
    h = __float2bfloat16(v);
    l = __float2bfloat16(v - __bfloat162float(h));
}
__device__ __forceinline__ void mma16816(float c[4], u32 a0,u32 a1,u32 a2,u32 a3,
                                         u32 b0,u32 b1){
    asm volatile(
      "mma.sync.aligned.m16n8k16.row.col.f32.bf16.bf16.f32 "
      "{%0,%1,%2,%3}, {%4,%5,%6,%7}, {%8,%9}, {%0,%1,%2,%3};"
      : "+f"(c[0]), "+f"(c[1]), "+f"(c[2]), "+f"(c[3])
      : "r"(a0), "r"(a1), "r"(a2), "r"(a3), "r"(b0), "r"(b1));
}

// ======================= Tensor-core GEMM (R14-exact, 2 CTA/SM) ============
// C[m,n] = A[m,:512] @ W[:512,n] + bias[n]
// MODE 0: A = x,  N=1536, epilogue split-scatters into g_Q/K/V (Q x 1/8).
// MODE 1: A = g_O, N=512, epilogue writes fp32 + bias to C.
#define OFF_AH 0
#define OFF_AL 10240
#define OFF_BH 20480
#define OFF_BL 30720
#define OFF_WF 40960
#define GEMM_SMEM (40960 + 32*132*4)   // 57856 B

template<int MODE>
__global__ __launch_bounds__(256, 2)
void gemm_tc3(const float* __restrict__ Ain,
              const float* __restrict__ W,
              const float* __restrict__ bias,
              float* __restrict__ C)
{
    extern __shared__ char gsm[];
    __nv_bfloat16* Ah = (__nv_bfloat16*)(gsm + OFF_AH);
    __nv_bfloat16* Al = (__nv_bfloat16*)(gsm + OFF_AL);
    __nv_bfloat16* Bh = (__nv_bfloat16*)(gsm + OFF_BH);
    __nv_bfloat16* Bl = (__nv_bfloat16*)(gsm + OFF_BL);
    float*         Wf = (float*)        (gsm + OFF_WF);

    constexpr int NSTR = (MODE == 0) ? 1536 : 512;
    const float* A = (MODE == 0) ? Ain : g_O;

    const int t = threadIdx.x;
    const int lane = t & 31, w = t >> 5;
    const int grp = lane >> 2, cc = lane & 3;
    const int wm = w & 3, wn = w >> 2;
    const int n0 = blockIdx.x * 128;
    const int m0 = blockIdx.y * 128;

    if (MODE == 0 && blockIdx.x == 0 && blockIdx.y == 0 && t < 64) g_maxKi[t] = 0;

    float c[2][8][4];
#pragma unroll
    for (int mi = 0; mi < 2; mi++)
#pragma unroll
        for (int ni = 0; ni < 8; ni++)
#pragma unroll
            for (int e = 0; e < 4; e++) c[mi][ni][e] = 0.f;

    for (int k0 = 0; k0 < 512; k0 += 32) {
        __syncthreads();
#pragma unroll
        for (int it = 0; it < 4; it++) {
            int i = t + it * 256;
            int m = i >> 3, kv = (i & 7) * 4;
            float4 v = *(const float4*)(A + (size_t)(m0 + m) * 512 + k0 + kv);
            __nv_bfloat16 h0,l0,h1,l1,h2,l2,h3,l3;
            split_bf(v.x, h0, l0); split_bf(v.y, h1, l1);
            split_bf(v.z, h2, l2); split_bf(v.w, h3, l3);
            *(u32*)&Ah[m * 40 + kv]     = pack2(h0, h1);
            *(u32*)&Ah[m * 40 + kv + 2] = pack2(h2, h3);
            *(u32*)&Al[m * 40 + kv]     = pack2(l0, l1);
            *(u32*)&Al[m * 40 + kv + 2] = pack2(l2, l3);
        }
#pragma unroll
        for (int it = 0; it < 4; it++) {
            int i = t + it * 256;
            int k = i >> 5, nv = (i & 31) * 4;
            *(float4*)&Wf[k * 132 + nv] =
                *(const float4*)(W + (size_t)(k0 + k) * NSTR + n0 + nv);
        }
        __syncthreads();
#pragma unroll
        for (int it = 0; it < 4; it++) {
            int i = t + it * 256;
            int n = i & 127, kb = (i >> 7) * 4;
            float v0 = Wf[(kb + 0) * 132 + n];
            float v1 = Wf[(kb + 1) * 132 + n];
            float v2 = Wf[(kb + 2) * 132 + n];
            float v3 = Wf[(kb + 3) * 132 + n];
            __nv_bfloat16 h0,l0,h1,l1,h2,l2,h3,l3;
            split_bf(v0, h0, l0); split_bf(v1, h1, l1);
            split_bf(v2, h2, l2); split_bf(v3, h3, l3);
            *(u32*)&Bh[n * 40 + kb]     = pack2(h0, h1);
            *(u32*)&Bh[n * 40 + kb + 2] = pack2(h2, h3);
            *(u32*)&Bl[n * 40 + kb]     = pack2(l0, l1);
            *(u32*)&Bl[n * 40 + kb + 2] = pack2(l2, l3);
        }
        __syncthreads();

#pragma unroll
        for (int ks = 0; ks < 2; ks++) {
            int col = ks * 16 + 2 * cc;
            u32 ah[2][4], al[2][4];
#pragma unroll
            for (int mi = 0; mi < 2; mi++) {
                int r = wm * 32 + mi * 16 + grp;
                ah[mi][0] = *(u32*)&Ah[r * 40 + col];
                ah[mi][1] = *(u32*)&Ah[(r + 8) * 40 + col];
                ah[mi][2] = *(u32*)&Ah[r * 40 + col + 8];
                ah[mi][3] = *(u32*)&Ah[(r + 8) * 40 + col + 8];
                al[mi][0] = *(u32*)&Al[r * 40 + col];
                al[mi][1] = *(u32*)&Al[(r + 8) * 40 + col];
                al[mi][2] = *(u32*)&Al[r * 40 + col + 8];
                al[mi][3] = *(u32*)&Al[(r + 8) * 40 + col + 8];
            }
#pragma unroll
            for (int ni = 0; ni < 8; ni++) {
                int nr = wn * 64 + ni * 8 + grp;
                u32 bh0 = *(u32*)&Bh[nr * 40 + col];
                u32 bh1 = *(u32*)&Bh[nr * 40 + col + 8];
                u32 bl0 = *(u32*)&Bl[nr * 40 + col];
                u32 bl1 = *(u32*)&Bl[nr * 40 + col + 8];
#pragma unroll
                for (int mi = 0; mi < 2; mi++) {
                    mma16816(c[mi][ni], ah[mi][0],ah[mi][1],ah[mi][2],ah[mi][3], bh0,bh1);
                    mma16816(c[mi][ni], ah[mi][0],ah[mi][1],ah[mi][2],ah[mi][3], bl0,bl1);
                    mma16816(c[mi][ni], al[mi][0],al[mi][1],al[mi][2],al[mi][3], bh0,bh1);
                }
            }
        }
    }

#pragma unroll
    for (int mi = 0; mi < 2; mi++) {
        int r0 = m0 + wm * 32 + mi * 16 + grp;
#pragma unroll
        for (int ni = 0; ni < 8; ni++) {
            int ng = n0 + wn * 64 + ni * 8 + 2 * cc;
            float b0 = bias[ng], b1 = bias[ng + 1];
            if (MODE == 0) {
                int part = ng >> 9;
                int rr = ng & 511;
                int hd = rr >> 6, d = rr & 63;
                float sc = (part == 0) ? 0.125f : 1.f;
                __nv_bfloat16* H = (part == 0) ? g_Qh : (part == 1) ? g_Kh : g_Vh;
                __nv_bfloat16* L = (part == 0) ? g_Ql : (part == 1) ? g_Kl : g_Vl;
#pragma unroll
                for (int rr2 = 0; rr2 < 2; rr2++) {
                    int m = r0 + rr2 * 8;
                    int bb = m >> 10, s = m & 1023;
                    float v0 = (c[mi][ni][2*rr2 + 0] + b0) * sc;
                    float v1 = (c[mi][ni][2*rr2 + 1] + b1) * sc;
                    __nv_bfloat16 h0,l0,h1,l1;
                    split_bf(v0, h0, l0); split_bf(v1, h1, l1);
                    size_t off = ((size_t)(bb*8 + hd) * 1024 + s) * 64 + d;
                    *(u32*)(H + off) = pack2(h0, h1);
                    *(u32*)(L + off) = pack2(l0, l1);
                }
            } else {
#pragma unroll
                for (int rr2 = 0; rr2 < 2; rr2++) {
                    int m = r0 + rr2 * 8;
                    float2 v = make_float2(c[mi][ni][2*rr2 + 0] + b0,
                                           c[mi][ni][2*rr2 + 1] + b1);
                    *(float2*)(C + (size_t)m * 512 + ng) = v;
                }
            }
        }
    }
}

// ======================= Kernel 1b: V transpose + K norms ==================
__global__ __launch_bounds__(256)
void vtrans_kernel()
{
    __shared__ __nv_bfloat16 th[64][72];
    __shared__ __nv_bfloat16 tl[64][72];
    const int t = threadIdx.x;
    const int s0 = blockIdx.x * 64;
    const int bh = blockIdx.y;

    for (int i = t; i < 2048; i += 256) {
        int sl = i >> 5, dp = i & 31;
        size_t src = ((size_t)bh * 1024 + s0 + sl) * 64 + 2*dp;
        *(u32*)&th[sl][2*dp] = *(const u32*)(g_Vh + src);
        *(u32*)&tl[sl][2*dp] = *(const u32*)(g_Vl + src);
    }
    __syncthreads();
    for (int i = t; i < 2048; i += 256) {
        int d = i >> 5, sp = i & 31;
        size_t dst = ((size_t)bh * 64 + d) * 1024 + s0 + 2*sp;
        *(u32*)(g_Vth + dst) = pack2(th[2*sp][d], th[2*sp+1][d]);
        *(u32*)(g_Vtl + dst) = pack2(tl[2*sp][d], tl[2*sp+1][d]);
    }
    if (t < 64) {
        float s = 0.f;
        size_t base = ((size_t)bh * 1024 + s0 + t) * 64;
        for (int dp = 0; dp < 32; dp++) {
            float2 h = unpack2(*(const u32*)(g_Kh + base + 2*dp));
            float2 l = unpack2(*(const u32*)(g_Kl + base + 2*dp));
            float v0 = h.x + l.x, v1 = h.y + l.y;
            s += v0*v0 + v1*v1;
        }
        atomicMax(&g_maxKi[bh], __float_as_int(sqrtf(s)));
    }
}

// ======================= Kernel 2: attention, full register prefetch =======
// R14 main-loop prefetch + NEW: posK prefetch in Qp phase, posV in O2 phase.
#define OFF_QH 0
#define OFF_QL 9216
#define OFF_KH 18432
#define OFF_KL 27648
#define OFF_VH 36864
#define OFF_VL 46080
#define OFF_QP 55296
#define OFF_AP 122880
#define OFF_MSK 190464
#define OFF_RED 190720
#define ATTN_SMEM (190720 + 4096)

__global__ __launch_bounds__(512)
void attn_kernel(const int* __restrict__ mask,
                 const float* __restrict__ posK,
                 const float* __restrict__ posV)
{
    extern __shared__ char sm[];
    __nv_bfloat16* QH = (__nv_bfloat16*)(sm + OFF_QH);
    __nv_bfloat16* QL = (__nv_bfloat16*)(sm + OFF_QL);
    __nv_bfloat16* KH = (__nv_bfloat16*)(sm + OFF_KH);
    __nv_bfloat16* KL = (__nv_bfloat16*)(sm + OFF_KL);
    __nv_bfloat16* VH = (__nv_bfloat16*)(sm + OFF_VH);
    __nv_bfloat16* VL = (__nv_bfloat16*)(sm + OFF_VL);
    float* QP  = (float*)(sm + OFF_QP);
    float* AP  = (float*)(sm + OFF_AP);
    float* MSK = (float*)(sm + OFF_MSK);
    float* RED = (float*)(sm + OFF_RED);

    const int t = threadIdx.x;
    const int w = t >> 5, lane = t & 31, grp = lane >> 2, cc = lane & 3;
    const int wq = w & 3, wn = w >> 2;
    const int q0 = blockIdx.x * 64;
    const int bh = blockIdx.y;
    const int bb = bh >> 3, hh = bh & 7;
    const int r_lo = wq * 16 + grp;
    const int qg0 = q0 + r_lo, qg1 = qg0 + 8;
    const int sk0 = t >> 5, sdp = (t & 31);

    for (int i = t; i < 2048; i += 512) {
        int r = i >> 5, dp = i & 31;
        size_t src = ((size_t)bh * 1024 + q0 + r) * 64 + 2*dp;
        *(u32*)&QH[r*72 + 2*dp] = *(const u32*)(g_Qh + src);
        *(u32*)&QL[r*72 + 2*dp] = *(const u32*)(g_Ql + src);
    }
    for (int i = t; i < 64*264; i += 512) AP[i] = 0.f;
    __syncthreads();

    u32 qa_h[4][4], qa_l[4][4];
#pragma unroll
    for (int kc = 0; kc < 4; kc++) {
        int col = 16*kc + 2*cc;
        qa_h[kc][0] = *(u32*)&QH[ r_lo    *72 + col];
        qa_h[kc][1] = *(u32*)&QH[(r_lo+8)*72 + col];
        qa_h[kc][2] = *(u32*)&QH[ r_lo    *72 + col + 8];
        qa_h[kc][3] = *(u32*)&QH[(r_lo+8)*72 + col + 8];
        qa_l[kc][0] = *(u32*)&QL[ r_lo    *72 + col];
        qa_l[kc][1] = *(u32*)&QL[(r_lo+8)*72 + col];
        qa_l[kc][2] = *(u32*)&QL[ r_lo    *72 + col + 8];
        qa_l[kc][3] = *(u32*)&QL[(r_lo+8)*72 + col + 8];
    }

    // ---- Qp phase with posK register prefetch ----
    {
        float2 pP[4];
#pragma unroll
        for (int j = 0; j < 4; j++) {
            int rg = sk0 + 16*j;    // rt = 0
            pP[j] = (rg < 257) ? *(const float2*)(posK + rg*64 + 2*sdp)
                               : make_float2(0.f, 0.f);
        }
        for (int rt = 0; rt < 5; rt++) {
            int r0 = rt * 64;
            __syncthreads();
#pragma unroll
            for (int j = 0; j < 4; j++) {
                int r = sk0 + 16*j;
                __nv_bfloat16 h0,l0,h1,l1;
                split_bf(pP[j].x, h0, l0); split_bf(pP[j].y, h1, l1);
                *(u32*)&KH[r*72 + 2*sdp] = pack2(h0, h1);
                *(u32*)&KL[r*72 + 2*sdp] = pack2(l0, l1);
            }
            __syncthreads();
            if (rt < 4) {
                int r0n = (rt + 1) * 64;
#pragma unroll
                for (int j = 0; j < 4; j++) {
                    int rg = r0n + sk0 + 16*j;
                    pP[j] = (rg < 257) ? *(const float2*)(posK + rg*64 + 2*sdp)
                                       : make_float2(0.f, 0.f);
                }
            }
            float c[2][4];
#pragma unroll
            for (int n4 = 0; n4 < 2; n4++)
#pragma unroll
                for (int e = 0; e < 4; e++) c[n4][e] = 0.f;
#pragma unroll
            for (int n4 = 0; n4 < 2; n4++) {
                int nc = 2*wn + n4;
#pragma unroll
                for (int kc = 0; kc < 4; kc++) {
                    const __nv_bfloat16* ph = KH + (8*nc+grp)*72 + 16*kc + 2*cc;
                    const __nv_bfloat16* pl = KL + (8*nc+grp)*72 + 16*kc + 2*cc;
                    u32 bh0 = *(const u32*)ph, bh1 = *(const u32*)(ph + 8);
                    u32 bl0 = *(const u32*)pl, bl1 = *(const u32*)(pl + 8);
                    mma16816(c[n4], qa_h[kc][0],qa_h[kc][1],qa_h[kc][2],qa_h[kc][3], bh0,bh1);
                    mma16816(c[n4], qa_h[kc][0],qa_h[kc][1],qa_h[kc][2],qa_h[kc][3], bl0,bl1);
                    mma16816(c[n4], qa_l[kc][0],qa_l[kc][1],qa_l[kc][2],qa_l[kc][3], bh0,bh1);
                }
            }
#pragma unroll
            for (int n4 = 0; n4 < 2; n4++) {
                int nc = 2*wn + n4;
                int r = r0 + 8*nc + 2*cc;
                if (r < 257) {
                    QP[ r_lo    *264 + r] = c[n4][0];
                    QP[(r_lo+8) *264 + r] = c[n4][2];
                }
                if (r + 1 < 257) {
                    QP[ r_lo    *264 + r + 1] = c[n4][1];
                    QP[(r_lo+8) *264 + r + 1] = c[n4][3];
                }
            }
        }
    }

    __syncthreads();
    {
        const float maxK = __int_as_float(g_maxKi[bh]);
        if (t < 64) {
            float sn = 0.f;
            for (int dp = 0; dp < 32; dp++) {
                float2 h = unpack2(*(u32*)&QH[t*72 + 2*dp]);
                float2 l = unpack2(*(u32*)&QL[t*72 + 2*dp]);
                float v0 = h.x + l.x, v1 = h.y + l.y;
                sn += v0*v0 + v1*v1;
            }
            float mq = -1e30f;
            for (int r = 0; r < 257; r++) mq = fmaxf(mq, QP[t*264 + r]);
            RED[t] = sqrtf(sn) * maxK + mq + 0.5f;
        }
    }
    __syncthreads();
    const float z0 = RED[r_lo], z1 = RED[r_lo + 8];
    __syncthreads();

    float o[8][4];
#pragma unroll
    for (int nd = 0; nd < 8; nd++)
#pragma unroll
        for (int e = 0; e < 4; e++) o[nd][e] = 0.f;
    float bin0a = 0.f, bin0b = 0.f, bin256a = 0.f, bin256b = 0.f;
    float ls0 = 0.f, ls1 = 0.f;

    // ---- main loop with K/V register prefetch (R14-validated) ----
    u32 pK[4][2], pV[4][2];
#pragma unroll
    for (int j = 0; j < 4; j++) {
        int k = sk0 + 16*j;
        size_t srcK = ((size_t)bh * 1024 + k) * 64 + 2*sdp;
        size_t srcV = ((size_t)bh * 64 + k) * 1024 + 2*sdp;
        pK[j][0] = *(const u32*)(g_Kh + srcK);
        pK[j][1] = *(const u32*)(g_Kl + srcK);
        pV[j][0] = *(const u32*)(g_Vth + srcV);
        pV[j][1] = *(const u32*)(g_Vtl + srcV);
    }
    int pmsk = (t < 64) ? mask[bb*1024 + t] : 0;

    for (int kt = 0; kt < 16; kt++) {
        __syncthreads();
#pragma unroll
        for (int j = 0; j < 4; j++) {
            int k = sk0 + 16*j;
            *(u32*)&KH[k*72 + 2*sdp] = pK[j][0];
            *(u32*)&KL[k*72 + 2*sdp] = pK[j][1];
            *(u32*)&VH[k*72 + 2*sdp] = pV[j][0];
            *(u32*)&VL[k*72 + 2*sdp] = pV[j][1];
        }
        if (t < 64) MSK[t] = pmsk ? 0.f : -1e30f;
        __syncthreads();
        if (kt < 15) {
            int k0n = (kt + 1) * 64;
#pragma unroll
            for (int j = 0; j < 4; j++) {
                int k = sk0 + 16*j;
                size_t srcK = ((size_t)bh * 1024 + k0n + k) * 64 + 2*sdp;
                size_t srcV = ((size_t)bh * 64 + k) * 1024 + k0n + 2*sdp;
                pK[j][0] = *(const u32*)(g_Kh + srcK);
                pK[j][1] = *(const u32*)(g_Kl + srcK);
                pV[j][0] = *(const u32*)(g_Vth + srcV);
                pV[j][1] = *(const u32*)(g_Vtl + srcV);
            }
            if (t < 64) pmsk = mask[bb*1024 + k0n + t];
        }

        const int k0 = kt * 64;
        float c[2][4];
#pragma unroll
        for (int n4 = 0; n4 < 2; n4++)
#pragma unroll
            for (int e = 0; e < 4; e++) c[n4][e] = 0.f;
#pragma unroll
        for (int n4 = 0; n4 < 2; n4++) {
            int nc = 2*wn + n4;
#pragma unroll
            for (int kc = 0; kc < 4; kc++) {
                const __nv_bfloat16* ph = KH + (8*nc+grp)*72 + 16*kc + 2*cc;
                const __nv_bfloat16* pl = KL + (8*nc+grp)*72 + 16*kc + 2*cc;
                u32 bh0 = *(const u32*)ph, bh1 = *(const u32*)(ph + 8);
                u32 bl0 = *(const u32*)pl, bl1 = *(const u32*)(pl + 8);
                mma16816(c[n4], qa_h[kc][0],qa_h[kc][1],qa_h[kc][2],qa_h[kc][3], bh0,bh1);
                mma16816(c[n4], qa_h[kc][0],qa_h[kc][1],qa_h[kc][2],qa_h[kc][3], bl0,bl1);
                mma16816(c[n4], qa_l[kc][0],qa_l[kc][1],qa_l[kc][2],qa_l[kc][3], bh0,bh1);
            }
        }

        u32 ph[2][2], pl[2][2];
#pragma unroll
        for (int n4 = 0; n4 < 2; n4++) {
            int nc = 2*wn + n4;
            int kg = k0 + 8*nc + 2*cc;
            float bias0 = MSK[8*nc + 2*cc], bias1 = MSK[8*nc + 2*cc + 1];
            int dA0 = kg     - qg0, dA1 = kg + 1 - qg0;
            int dB0 = kg     - qg1, dB1 = kg + 1 - qg1;
            float s00 = c[n4][0] + QP[ r_lo   *264 + min(max(dA0,-128),128)+128] + bias0;
            float s01 = c[n4][1] + QP[ r_lo   *264 + min(max(dA1,-128),128)+128] + bias1;
            float s10 = c[n4][2] + QP[(r_lo+8)*264 + min(max(dB0,-128),128)+128] + bias0;
            float s11 = c[n4][3] + QP[(r_lo+8)*264 + min(max(dB1,-128),128)+128] + bias1;
            float p00 = __expf(s00 - z0), p01 = __expf(s01 - z0);
            float p10 = __expf(s10 - z1), p11 = __expf(s11 - z1);
            ls0 += p00 + p01;
            ls1 += p10 + p11;
            if (dA0 <= -128) bin0a += p00; else if (dA0 >= 128) bin256a += p00;
            else AP[ r_lo   *264 + dA0 + 128] = p00;
            if (dA1 <= -128) bin0a += p01; else if (dA1 >= 128) bin256a += p01;
            else AP[ r_lo   *264 + dA1 + 128] = p01;
            if (dB0 <= -128) bin0b += p10; else if (dB0 >= 128) bin256b += p10;
            else AP[(r_lo+8)*264 + dB0 + 128] = p10;
            if (dB1 <= -128) bin0b += p11; else if (dB1 >= 128) bin256b += p11;
            else AP[(r_lo+8)*264 + dB1 + 128] = p11;
            __nv_bfloat16 h00,l00,h01,l01,h10,l10,h11,l11;
            split_bf(p00, h00, l00); split_bf(p01, h01, l01);
            split_bf(p10, h10, l10); split_bf(p11, h11, l11);
            ph[n4][0] = pack2(h00, h01); pl[n4][0] = pack2(l00, l01);
            ph[n4][1] = pack2(h10, h11); pl[n4][1] = pack2(l10, l11);
        }

#pragma unroll
        for (int nd = 0; nd < 8; nd++) {
            const __nv_bfloat16* pvh = VH + (8*nd+grp)*72 + 16*wn + 2*cc;
            const __nv_bfloat16* pvl = VL + (8*nd+grp)*72 + 16*wn + 2*cc;
            u32 bh0 = *(const u32*)pvh, bh1 = *(const u32*)(pvh + 8);
            u32 bl0 = *(const u32*)pvl, bl1 = *(const u32*)(pvl + 8);
            mma16816(o[nd], ph[0][0], ph[0][1], ph[1][0], ph[1][1], bh0, bh1);
            mma16816(o[nd], ph[0][0], ph[0][1], ph[1][0], ph[1][1], bl0, bl1);
            mma16816(o[nd], pl[0][0], pl[0][1], pl[1][0], pl[1][1], bh0, bh1);
        }
    }

    bin0a   += __shfl_xor_sync(0xffffffffu, bin0a, 1);
    bin0a   += __shfl_xor_sync(0xffffffffu, bin0a, 2);
    bin0b   += __shfl_xor_sync(0xffffffffu, bin0b, 1);
    bin0b   += __shfl_xor_sync(0xffffffffu, bin0b, 2);
    bin256a += __shfl_xor_sync(0xffffffffu, bin256a, 1);
    bin256a += __shfl_xor_sync(0xffffffffu, bin256a, 2);
    bin256b += __shfl_xor_sync(0xffffffffu, bin256b, 1);
    bin256b += __shfl_xor_sync(0xffffffffu, bin256b, 2);
    ls0 += __shfl_xor_sync(0xffffffffu, ls0, 1);
    ls0 += __shfl_xor_sync(0xffffffffu, ls0, 2);
    ls1 += __shfl_xor_sync(0xffffffffu, ls1, 1);
    ls1 += __shfl_xor_sync(0xffffffffu, ls1, 2);
    if (cc == 0) {
        atomicAdd(&AP[ r_lo   *264 + 0],   bin0a);
        atomicAdd(&AP[ r_lo   *264 + 256], bin256a);
        atomicAdd(&AP[(r_lo+8)*264 + 0],   bin0b);
        atomicAdd(&AP[(r_lo+8)*264 + 256], bin256b);
        RED[wn*64 + r_lo]     = ls0;
        RED[wn*64 + r_lo + 8] = ls1;
    }
    __syncthreads();
    const float inv0 = 1.f / (RED[r_lo]       + RED[64 + r_lo] +
                              RED[128 + r_lo] + RED[192 + r_lo]);
    const float inv1 = 1.f / (RED[r_lo + 8]       + RED[64 + r_lo + 8] +
                              RED[128 + r_lo + 8] + RED[192 + r_lo + 8]);

    // ---- O2 phase with posV register prefetch ----
    {
        const int vr0 = t >> 6, vd = t & 63;     // r = vr0 + 8j
        float pPV[8];
#pragma unroll
        for (int j = 0; j < 8; j++) {
            int rg = vr0 + 8*j;                   // rt = 0
            pPV[j] = (rg < 257) ? posV[rg*64 + vd] : 0.f;
        }
        for (int rt = 0; rt < 5; rt++) {
            int r0 = rt * 64;
            // previous compute's readers drained by the sync at end of prior iter
#pragma unroll
            for (int j = 0; j < 8; j++) {
                int r = vr0 + 8*j;
                __nv_bfloat16 hb, lb;
                split_bf(pPV[j], hb, lb);
                VH[vd*72 + r] = hb;
                VL[vd*72 + r] = lb;
            }
            __syncthreads();
            if (rt < 4) {
                int r0n = (rt + 1) * 64;
#pragma unroll
                for (int j = 0; j < 8; j++) {
                    int rg = r0n + vr0 + 8*j;
                    pPV[j] = (rg < 257) ? posV[rg*64 + vd] : 0.f;
                }
            }
            {
                int rA = r0 + 16*wn + 2*cc;
                float v00 = (rA     < 257) ? AP[ r_lo   *264 + rA]     : 0.f;
                float v01 = (rA + 1 < 257) ? AP[ r_lo   *264 + rA + 1] : 0.f;
                float v10 = (rA     < 257) ? AP[(r_lo+8)*264 + rA]     : 0.f;
                float v11 = (rA + 1 < 257) ? AP[(r_lo+8)*264 + rA + 1] : 0.f;
                float v20 = (rA + 8 < 257) ? AP[ r_lo   *264 + rA + 8] : 0.f;
                float v21 = (rA + 9 < 257) ? AP[ r_lo   *264 + rA + 9] : 0.f;
                float v30 = (rA + 8 < 257) ? AP[(r_lo+8)*264 + rA + 8] : 0.f;
                float v31 = (rA + 9 < 257) ? AP[(r_lo+8)*264 + rA + 9] : 0.f;
                __nv_bfloat16 h[8], l[8];
                split_bf(v00, h[0], l[0]); split_bf(v01, h[1], l[1]);
                split_bf(v10, h[2], l[2]); split_bf(v11, h[3], l[3]);
                split_bf(v20, h[4], l[4]); split_bf(v21, h[5], l[5]);
                split_bf(v30, h[6], l[6]); split_bf(v31, h[7], l[7]);
                u32 ah0 = pack2(h[0], h[1]), ah1 = pack2(h[2], h[3]);
                u32 ah2 = pack2(h[4], h[5]), ah3 = pack2(h[6], h[7]);
                u32 al0 = pack2(l[0], l[1]), al1 = pack2(l[2], l[3]);
                u32 al2 = pack2(l[4], l[5]), al3 = pack2(l[6], l[7]);
#pragma unroll
                for (int nd = 0; nd < 8; nd++) {
                    const __nv_bfloat16* pvh = VH + (8*nd+grp)*72 + 16*wn + 2*cc;
                    const __nv_bfloat16* pvl = VL + (8*nd+grp)*72 + 16*wn + 2*cc;
                    u32 bh0 = *(const u32*)pvh, bh1 = *(const u32*)(pvh + 8);
                    u32 bl0 = *(const u32*)pvl, bl1 = *(const u32*)(pvl + 8);
                    mma16816(o[nd], ah0, ah1, ah2, ah3, bh0, bh1);
                    mma16816(o[nd], ah0, ah1, ah2, ah3, bl0, bl1);
                    mma16816(o[nd], al0, al1, al2, al3, bh0, bh1);
                }
            }
            __syncthreads();
        }
    }

    float* SC = QP;
    if (wn > 0) {
#pragma unroll
        for (int nd = 0; nd < 8; nd++)
            *(float4*)&SC[(wn-1)*4096 + wq*1024 + nd*128 + lane*4] = *(float4*)&o[nd][0];
    }
    __syncthreads();
    if (wn == 0) {
#pragma unroll
        for (int nd = 0; nd < 8; nd++) {
            float4 p1 = *(float4*)&SC[        wq*1024 + nd*128 + lane*4];
            float4 p2 = *(float4*)&SC[4096  + wq*1024 + nd*128 + lane*4];
            float4 p3 = *(float4*)&SC[8192  + wq*1024 + nd*128 + lane*4];
            int d = hh*64 + 8*nd + 2*cc;
            float2 s0 = make_float2((o[nd][0] + p1.x + p2.x + p3.x) * inv0,
                                    (o[nd][1] + p1.y + p2.y + p3.y) * inv0);
            float2 s1 = make_float2((o[nd][2] + p1.z + p2.z + p3.z) * inv1,
                                    (o[nd][3] + p1.w + p2.w + p3.w) * inv1);
            *(float2*)&g_O[((size_t)bb*1024 + q0 + r_lo    ) * 512 + d] = s0;
            *(float2*)&g_O[((size_t)bb*1024 + q0 + r_lo + 8) * 512 + d] = s1;
        }
    }
}

// ============================== launcher ===================================
extern "C" void kernel_launch(void* const* d_in, const int* in_sizes, int n_in,
                              void* d_out, int out_size)
{
    const float* x     = (const float*)d_in[0];
    const int*   mask  = (const int*)  d_in[1];
    const float* W_in  = (const float*)d_in[2];
    const float* b_in  = (const float*)d_in[3];
    const float* W_out = (const float*)d_in[4];
    const float* b_out = (const float*)d_in[5];
    const float* posK  = (const float*)d_in[6];
    const float* posV  = (const float*)d_in[7];
    float* out = (float*)d_out;
    (void)in_sizes; (void)n_in; (void)out_size;

    cudaFuncSetAttribute(attn_kernel,
                         cudaFuncAttributeMaxDynamicSharedMemorySize, ATTN_SMEM);
    cudaFuncSetAttribute(gemm_tc3<0>,
                         cudaFuncAttributeMaxDynamicSharedMemorySize, GEMM_SMEM);
    cudaFuncSetAttribute(gemm_tc3<1>,
                         cudaFuncAttributeMaxDynamicSharedMemorySize, GEMM_SMEM);

    gemm_tc3<0><<<dim3(12, 64), 256, GEMM_SMEM>>>(x, W_in, b_in, nullptr);
    vtrans_kernel<<<dim3(16, 64), 256>>>();
    attn_kernel<<<dim3(16, 64), 512, ATTN_SMEM>>>(mask, posK, posV);
    gemm_tc3<1><<<dim3(4, 64), 256, GEMM_SMEM>>>(nullptr, W_out, b_out, out);
}